// round 15
// baseline (speedup 1.0000x reference)
#include <cuda_runtime.h>
#include <cuda_fp16.h>
#include <math.h>

#define NN 8192
#define HH 128
#define FOUT 16
#define MAXDEG 256
#define KSEL 4096
#define BM 64
#define BN 64
#define BK 32
#define PGRID 592          // 148 SMs x 4 co-resident blocks (guaranteed by launch_bounds)
#define K1WORK 1280        // 256 GEMM tiles + 1024 scan groups

// ---------------- scratch (device globals; no allocation) ----------------
__device__ int      d_ell[(size_t)NN * MAXDEG];
__device__ int      d_deg[NN];          // atomic append counter == final degree
__device__ float    d_g0[(size_t)NN * HH];
__device__ float    d_h0[(size_t)NN * HH];
__device__ float    d_s[NN];
__device__ float    d_gate[NN];
__device__ int      d_mask[NN];
__device__ __half   d_qh[(size_t)NN * HH];
__device__ __half   d_xuh[(size_t)NN * HH];
__device__ float    d_z[(size_t)NN * HH];
__device__ float    d_gf[(size_t)NN * FOUT];
__device__ unsigned d_g0ctr;            // persistent-K1 barrier (target PGRID)

// ---------------- shared layouts ----------------
struct GemmSh {
    float As[BK][BM + 1];
    float Bs[BK][BN];
};
struct SelSh {
    unsigned keys[NN];
    unsigned whist[8][256];
    unsigned suf[256];
    unsigned cnts[8];
    unsigned prefix, kk;
    float    inv_norm;
    float    red[8];
};
union SharedU {
    GemmSh g;
    SelSh  s;
};

#define ACC4(a, v) { (a).x += (v).x; (a).y += (v).y; (a).z += (v).z; (a).w += (v).w; }
#define FMA4(a, g, v) { (a).x += (g)*(v).x; (a).y += (g)*(v).y; (a).z += (g)*(v).z; (a).w += (g)*(v).w; }

// ---------------- half-row gather helper ----------------
__device__ __forceinline__ float4 ldh4(const uint2* __restrict__ base, size_t row, int lane) {
    uint2 u = base[row * 32 + lane];
    __half2 h0 = *reinterpret_cast<__half2*>(&u.x);
    __half2 h1 = *reinterpret_cast<__half2*>(&u.y);
    float2 f0 = __half22float2(h0);
    float2 f1 = __half22float2(h1);
    return make_float4(f0.x, f0.y, f1.x, f1.y);
}

// ---------------- GEMM body (templated fp32/fp16 output) ----------------
template <bool HALFOUT>
__device__ __forceinline__ void gemm_body(GemmSh& sh,
                                          const float* __restrict__ Ain,
                                          const float* __restrict__ B,
                                          const float* __restrict__ bias,
                                          void* __restrict__ C,
                                          int K, int Nc, int m0, int n0) {
    int tid = threadIdx.x;
    int tx = tid & 15, ty = tid >> 4;
    float acc[4][4] = {};
    for (int k0 = 0; k0 < K; k0 += BK) {
        #pragma unroll
        for (int t = 0; t < 8; t++) {
            int li = tid + t * 256;
            int m = li >> 5, kk = li & 31;
            sh.As[kk][m] = Ain[(size_t)(m0 + m) * K + (k0 + kk)];
        }
        #pragma unroll
        for (int t = 0; t < 8; t++) {
            int li = tid + t * 256;
            int kk = li >> 6, n = li & 63;
            sh.Bs[kk][n] = (n0 + n < Nc) ? B[(size_t)(k0 + kk) * Nc + (n0 + n)] : 0.0f;
        }
        __syncthreads();
        #pragma unroll
        for (int kk = 0; kk < BK; kk++) {
            float a[4], b[4];
            #pragma unroll
            for (int i = 0; i < 4; i++) a[i] = sh.As[kk][ty * 4 + i];
            #pragma unroll
            for (int j = 0; j < 4; j++) b[j] = sh.Bs[kk][tx * 4 + j];
            #pragma unroll
            for (int i = 0; i < 4; i++)
                #pragma unroll
                for (int j = 0; j < 4; j++)
                    acc[i][j] += a[i] * b[j];
        }
        __syncthreads();
    }
    #pragma unroll
    for (int i = 0; i < 4; i++) {
        int m = m0 + ty * 4 + i;
        #pragma unroll
        for (int j = 0; j < 4; j++) {
            int n = n0 + tx * 4 + j;
            if (n < Nc) {
                float v = acc[i][j] + bias[n];
                if (HALFOUT) ((__half*)C)[(size_t)m * Nc + n] = __float2half(v);
                else         ((float*)C)[(size_t)m * Nc + n] = v;
            }
        }
    }
}

// ======== kernel 1 (PERSISTENT, 592 co-resident blocks) ======================
// Phase A: 1280 items = 256 GEMM0 tiles + 1024 symmetric scan groups.
//   Upper-triangle scan (cols > r): local append col->lst[r] (warp-aggregated
//   atomic position), remote append r->lst[col] (per-lane atomic position).
// Barrier: all PGRID blocks resident by construction -> counter barrier safe.
// Phase C: 1024 h0-aggregation groups (8 rows each) + fused score.
__global__ void __launch_bounds__(256, 4)
k1_persistent(const float* __restrict__ A,
              const float* __restrict__ x,
              const float* __restrict__ W0,
              const float* __restrict__ b0,
              const float* __restrict__ pw,
              const float* __restrict__ pbp,
              int* __restrict__ ell, int* __restrict__ deg,
              float* __restrict__ g0,
              float* __restrict__ h0,
              float* __restrict__ score) {
    __shared__ GemmSh sh;
    int wid = threadIdx.x >> 5;
    int lane = threadIdx.x & 31;

    // ---------------- phase A ----------------
    for (int w = blockIdx.x; w < K1WORK; w += PGRID) {
        if (w < 256) {
            gemm_body<false>(sh, x, W0, b0, g0, 256, HH, (w >> 1) * BM, (w & 1) * BN);
            __syncthreads();           // sh reused by next item
        } else {
            int r = (w - 256) * 8 + wid;
            const float* row = A + (size_t)r * NN;
            int* lst = ell + (size_t)r * MAXDEG;
            int c0 = (r >> 7) << 7;    // 128-aligned chunk containing r
            for (; c0 < NN; c0 += 128) {
                float4 v = *(const float4*)(row + c0 + lane * 4);
                int colb = c0 + lane * 4;
                unsigned nib = ((v.x != 0.0f && colb + 0 > r) ? 1u : 0u)
                             | ((v.y != 0.0f && colb + 1 > r) ? 2u : 0u)
                             | ((v.z != 0.0f && colb + 2 > r) ? 4u : 0u)
                             | ((v.w != 0.0f && colb + 3 > r) ? 8u : 0u);
                if (__ballot_sync(0xffffffffu, nib != 0u) == 0u) continue;
                #pragma unroll
                for (int u = 0; u < 4; u++) {
                    bool nz = (nib >> u) & 1u;
                    unsigned bl = __ballot_sync(0xffffffffu, nz);
                    if (bl == 0u) continue;
                    int leader = __ffs(bl) - 1;
                    int base = 0;
                    if (lane == leader) base = atomicAdd(&deg[r], __popc(bl));
                    base = __shfl_sync(0xffffffffu, base, leader);
                    if (nz) {
                        int col = colb + u;
                        int pos = base + __popc(bl & ((1u << lane) - 1u));
                        if (pos < MAXDEG) lst[pos] = col;
                        int rpos = atomicAdd(&deg[col], 1);
                        if (rpos < MAXDEG) ell[(size_t)col * MAXDEG + rpos] = r;
                    }
                }
            }
        }
    }

    // ---------------- barrier (all PGRID blocks co-resident => safe) ---------
    __threadfence();
    __syncthreads();
    if (threadIdx.x == 0) {
        atomicAdd(&d_g0ctr, 1u);
        int guard = 0;
        while (atomicAdd(&d_g0ctr, 0u) < (unsigned)PGRID && guard < (1 << 20)) {
            __nanosleep(64);
            guard++;
        }
    }
    __syncthreads();
    __threadfence();

    // ---------------- phase C: h0 = relu(norm_agg(g0)); score ----------------
    const float4* g4 = (const float4*)g0;
    for (int w = blockIdx.x; w < 1024; w += PGRID) {
        int r = w * 8 + wid;
        int dg = deg[r];
        dg = (dg < MAXDEG) ? dg : MAXDEG;
        const int* lst = ell + (size_t)r * MAXDEG;
        float4 acc0 = g4[(size_t)r * 32 + lane];
        float4 acc1 = {0.f, 0.f, 0.f, 0.f};
        int t = 0;
        for (; t + 8 <= dg; t += 8) {
            int4 ia = *(const int4*)(lst + t);
            int4 ib = *(const int4*)(lst + t + 4);
            float4 v0 = g4[(size_t)ia.x * 32 + lane];
            float4 v1 = g4[(size_t)ia.y * 32 + lane];
            float4 v2 = g4[(size_t)ia.z * 32 + lane];
            float4 v3 = g4[(size_t)ia.w * 32 + lane];
            float4 v4 = g4[(size_t)ib.x * 32 + lane];
            float4 v5 = g4[(size_t)ib.y * 32 + lane];
            float4 v6 = g4[(size_t)ib.z * 32 + lane];
            float4 v7 = g4[(size_t)ib.w * 32 + lane];
            ACC4(acc0, v0); ACC4(acc1, v1); ACC4(acc0, v2); ACC4(acc1, v3);
            ACC4(acc0, v4); ACC4(acc1, v5); ACC4(acc0, v6); ACC4(acc1, v7);
        }
        for (; t < dg; t++) {
            float4 v = g4[(size_t)lst[t] * 32 + lane];
            ACC4(acc0, v);
        }
        ACC4(acc0, acc1);
        float sc = 1.0f / (float)(1 + dg);
        acc0.x = fmaxf(acc0.x * sc, 0.0f);
        acc0.y = fmaxf(acc0.y * sc, 0.0f);
        acc0.z = fmaxf(acc0.z * sc, 0.0f);
        acc0.w = fmaxf(acc0.w * sc, 0.0f);
        ((float4*)h0)[(size_t)r * 32 + lane] = acc0;
        float4 wv = ((const float4*)pw)[lane];
        float dd = acc0.x * wv.x + acc0.y * wv.y + acc0.z * wv.z + acc0.w * wv.w;
        #pragma unroll
        for (int off = 16; off; off >>= 1) dd += __shfl_xor_sync(0xffffffffu, dd, off);
        if (lane == 0) score[r] = dd + pbp[0];
    }
}

// ---------------- selection body ----------------
__device__ __forceinline__ void select_body(SelSh& sh,
                                            const float* __restrict__ s,
                                            float* __restrict__ gate,
                                            int* __restrict__ mask) {
    int t = threadIdx.x;
    int warp = t >> 5, lane = t & 31;

    float ss = 0.0f;
    for (int i = t; i < NN; i += 256) {
        float v = s[i];
        unsigned u = __float_as_uint(v);
        u = (u & 0x80000000u) ? ~u : (u | 0x80000000u);
        sh.keys[i] = u;
        ss += v * v;
    }
    #pragma unroll
    for (int off = 16; off; off >>= 1) ss += __shfl_xor_sync(0xffffffffu, ss, off);
    if (lane == 0) sh.red[warp] = ss;
    __syncthreads();
    if (t == 0) {
        float tot = 0.0f;
        #pragma unroll
        for (int w = 0; w < 8; w++) tot += sh.red[w];
        sh.inv_norm = rsqrtf(tot);
        sh.prefix = 0;
        sh.kk = KSEL;
    }
    __syncthreads();

    unsigned maskbits = 0;
    for (int shift = 24; shift >= 0; shift -= 8) {
        for (int i = t; i < 8 * 256; i += 256) ((unsigned*)sh.whist)[i] = 0;
        __syncthreads();
        unsigned pref = sh.prefix;
        for (int i = t; i < NN; i += 256) {
            unsigned ky = sh.keys[i];
            if ((ky & maskbits) == pref)
                atomicAdd(&sh.whist[warp][(ky >> shift) & 255u], 1u);
        }
        __syncthreads();
        {
            unsigned h = 0;
            #pragma unroll
            for (int w = 0; w < 8; w++) h += sh.whist[w][t];
            sh.suf[t] = h;
        }
        __syncthreads();
        for (int off = 1; off < 256; off <<= 1) {
            unsigned v = sh.suf[t] + ((t + off < 256) ? sh.suf[t + off] : 0u);
            __syncthreads();
            sh.suf[t] = v;
            __syncthreads();
        }
        unsigned Sb  = sh.suf[t];
        unsigned Sb1 = (t < 255) ? sh.suf[t + 1] : 0u;
        unsigned kkv = sh.kk;
        __syncthreads();
        if (Sb >= kkv && Sb1 < kkv) {
            sh.prefix = pref | ((unsigned)t << shift);
            sh.kk = kkv - Sb1;
        }
        maskbits |= (0xFFu << shift);
        __syncthreads();
    }
    unsigned T = sh.prefix;
    unsigned need_eq = sh.kk;
    float inv_norm = sh.inv_norm;

    int base = t * 32;
    unsigned loc = 0;
    #pragma unroll
    for (int u = 0; u < 32; u++) loc += (sh.keys[base + u] == T) ? 1u : 0u;
    unsigned inc = loc;
    #pragma unroll
    for (int off = 1; off < 32; off <<= 1) {
        unsigned v = __shfl_up_sync(0xffffffffu, inc, off);
        if (lane >= off) inc += v;
    }
    if (lane == 31) sh.cnts[warp] = inc;
    __syncthreads();
    unsigned woff = 0;
    for (int w = 0; w < warp; w++) woff += sh.cnts[w];
    unsigned run = woff + inc - loc;

    #pragma unroll
    for (int u = 0; u < 32; u++) {
        int i = base + u;
        unsigned ky = sh.keys[i];
        int sel;
        if (ky > T) sel = 1;
        else if (ky == T) { sel = (run < need_eq) ? 1 : 0; run++; }
        else sel = 0;
        mask[i] = sel;
        float v = s[i] * inv_norm;
        gate[i] = sel ? (1.0f / (1.0f + expf(-v))) : 0.0f;
    }
}

// ---------------- fused kernel 2: select || Q = h0@W1 (fp16 out) -------------
__global__ void fused_select_gemmq(const float* __restrict__ s,
                                   float* __restrict__ gate, int* __restrict__ mask,
                                   const float* __restrict__ h0,
                                   const float* __restrict__ W1,
                                   const float* __restrict__ zero_bias,
                                   __half* __restrict__ Qh) {
    __shared__ SharedU sh;
    int b = blockIdx.x;
    if (b == 0) {
        select_body(sh.s, s, gate, mask);
    } else {
        int bb = b - 1;
        gemm_body<true>(sh.g, h0, W1, zero_bias, Qh, HH, HH, (bb >> 1) * BM, (bb & 1) * BN);
    }
}

// ======== pooled SpMM: fp16 Q gather, gate-predicated, fp16 xu out ===========
__global__ void __launch_bounds__(256)
spmm_pool4h_kernel(const __half* __restrict__ Q,
                   const int* __restrict__ deg,
                   const int* __restrict__ mask,
                   const float* __restrict__ gate,
                   const float* __restrict__ b1,
                   __half* __restrict__ xu) {
    __shared__ float4 part[8][32];
    __shared__ int    pcnt[8];
    int wid = threadIdx.x >> 5;
    int lane = threadIdx.x & 31;
    int rw = wid >> 2;
    int wq = wid & 3;
    int r = blockIdx.x * 2 + rw;
    int active = mask[r];
    const uint2* q2 = (const uint2*)Q;
    int dg = deg[r];
    dg = (dg < MAXDEG) ? dg : MAXDEG;
    const int* lst = d_ell + (size_t)r * MAXDEG;

    float4 acc = {0.f, 0.f, 0.f, 0.f};
    int cnt = 0;
    if (active) {
        if (wq == 0) {
            float gr = gate[r];
            float4 v = ldh4(q2, (size_t)r, lane);
            FMA4(acc, gr, v);
            cnt = 1;
        }
        int beg = (dg * wq) >> 2;
        int end = (dg * (wq + 1)) >> 2;
        int t = beg;
        for (; t + 8 <= end; t += 8) {
            int j0 = lst[t], j1 = lst[t+1], j2 = lst[t+2], j3 = lst[t+3];
            int j4 = lst[t+4], j5 = lst[t+5], j6 = lst[t+6], j7 = lst[t+7];
            float g0v = gate[j0], g1v = gate[j1], g2v = gate[j2], g3v = gate[j3];
            float g4v = gate[j4], g5v = gate[j5], g6v = gate[j6], g7v = gate[j7];
            float4 v0 = {0,0,0,0}, v1 = {0,0,0,0}, v2 = {0,0,0,0}, v3 = {0,0,0,0};
            float4 v4 = {0,0,0,0}, v5 = {0,0,0,0}, v6 = {0,0,0,0}, v7 = {0,0,0,0};
            if (g0v != 0.0f) v0 = ldh4(q2, (size_t)j0, lane);
            if (g1v != 0.0f) v1 = ldh4(q2, (size_t)j1, lane);
            if (g2v != 0.0f) v2 = ldh4(q2, (size_t)j2, lane);
            if (g3v != 0.0f) v3 = ldh4(q2, (size_t)j3, lane);
            if (g4v != 0.0f) v4 = ldh4(q2, (size_t)j4, lane);
            if (g5v != 0.0f) v5 = ldh4(q2, (size_t)j5, lane);
            if (g6v != 0.0f) v6 = ldh4(q2, (size_t)j6, lane);
            if (g7v != 0.0f) v7 = ldh4(q2, (size_t)j7, lane);
            FMA4(acc, g0v, v0); FMA4(acc, g1v, v1);
            FMA4(acc, g2v, v2); FMA4(acc, g3v, v3);
            FMA4(acc, g4v, v4); FMA4(acc, g5v, v5);
            FMA4(acc, g6v, v6); FMA4(acc, g7v, v7);
            cnt += (g0v != 0.0f) + (g1v != 0.0f) + (g2v != 0.0f) + (g3v != 0.0f)
                 + (g4v != 0.0f) + (g5v != 0.0f) + (g6v != 0.0f) + (g7v != 0.0f);
        }
        for (; t < end; t++) {
            int j = lst[t];
            float gj = gate[j];
            if (gj != 0.0f) {
                float4 v = ldh4(q2, (size_t)j, lane);
                FMA4(acc, gj, v);
                cnt++;
            }
        }
    }
    part[wid][lane] = acc;
    if (lane == 0) pcnt[wid] = cnt;
    __syncthreads();
    if (wq == 0) {
        uint2* o2 = (uint2*)xu;
        if (!active) {
            uint2 z = {0u, 0u};
            o2[(size_t)r * 32 + lane] = z;
        } else {
            float4 a = part[rw * 4 + 0][lane];
            float4 b = part[rw * 4 + 1][lane];
            float4 c = part[rw * 4 + 2][lane];
            float4 d = part[rw * 4 + 3][lane];
            float4 s;
            s.x = a.x + b.x + c.x + d.x;
            s.y = a.y + b.y + c.y + d.y;
            s.z = a.z + b.z + c.z + d.z;
            s.w = a.w + b.w + c.w + d.w;
            int ctot = pcnt[rw*4+0] + pcnt[rw*4+1] + pcnt[rw*4+2] + pcnt[rw*4+3];
            float sc = 1.0f / (float)ctot;
            float4 bv = ((const float4*)b1)[lane];
            s.x = fmaxf(s.x * sc + bv.x, 0.0f);
            s.y = fmaxf(s.y * sc + bv.y, 0.0f);
            s.z = fmaxf(s.z * sc + bv.z, 0.0f);
            s.w = fmaxf(s.w * sc + bv.w, 0.0f);
            __half2 h0 = __floats2half2_rn(s.x, s.y);
            __half2 h1 = __floats2half2_rn(s.z, s.w);
            uint2 o;
            o.x = *reinterpret_cast<unsigned*>(&h0);
            o.y = *reinterpret_cast<unsigned*>(&h1);
            o2[(size_t)r * 32 + lane] = o;
        }
    }
}

// ======== z = norm_agg(xu): fully unconditional fp16 gather ==================
__global__ void __launch_bounds__(256)
spmm4h_kernel(const __half* __restrict__ xu,
              const int* __restrict__ deg,
              float* __restrict__ z) {
    __shared__ float4 part[8][32];
    int wid = threadIdx.x >> 5;
    int lane = threadIdx.x & 31;
    int rw = wid >> 2;
    int wq = wid & 3;
    int r = blockIdx.x * 2 + rw;
    const uint2* x2 = (const uint2*)xu;
    int dg = deg[r];
    dg = (dg < MAXDEG) ? dg : MAXDEG;
    const int* lst = d_ell + (size_t)r * MAXDEG;
    int beg = (dg * wq) >> 2;
    int end = (dg * (wq + 1)) >> 2;

    float4 acc0 = {0.f, 0.f, 0.f, 0.f};
    float4 acc1 = {0.f, 0.f, 0.f, 0.f};
    if (wq == 0) acc0 = ldh4(x2, (size_t)r, lane);
    int t = beg;
    for (; t + 8 <= end; t += 8) {
        int j0 = lst[t], j1 = lst[t+1], j2 = lst[t+2], j3 = lst[t+3];
        int j4 = lst[t+4], j5 = lst[t+5], j6 = lst[t+6], j7 = lst[t+7];
        float4 v0 = ldh4(x2, (size_t)j0, lane);
        float4 v1 = ldh4(x2, (size_t)j1, lane);
        float4 v2 = ldh4(x2, (size_t)j2, lane);
        float4 v3 = ldh4(x2, (size_t)j3, lane);
        float4 v4 = ldh4(x2, (size_t)j4, lane);
        float4 v5 = ldh4(x2, (size_t)j5, lane);
        float4 v6 = ldh4(x2, (size_t)j6, lane);
        float4 v7 = ldh4(x2, (size_t)j7, lane);
        ACC4(acc0, v0); ACC4(acc1, v1); ACC4(acc0, v2); ACC4(acc1, v3);
        ACC4(acc0, v4); ACC4(acc1, v5); ACC4(acc0, v6); ACC4(acc1, v7);
    }
    for (; t < end; t++) {
        float4 v = ldh4(x2, (size_t)lst[t], lane);
        ACC4(acc0, v);
    }
    ACC4(acc0, acc1);
    part[wid][lane] = acc0;
    __syncthreads();
    if (wq == 0) {
        float4 a = part[rw * 4 + 0][lane];
        float4 b = part[rw * 4 + 1][lane];
        float4 c = part[rw * 4 + 2][lane];
        float4 d = part[rw * 4 + 3][lane];
        float4 s;
        s.x = a.x + b.x + c.x + d.x;
        s.y = a.y + b.y + c.y + d.y;
        s.z = a.z + b.z + c.z + d.z;
        s.w = a.w + b.w + c.w + d.w;
        float sc = 1.0f / (float)(1 + dg);
        s.x *= sc; s.y *= sc; s.z *= sc; s.w *= sc;
        ((float4*)z)[(size_t)r * 32 + lane] = s;
    }
}

// ======== fused up-path GEMM: gf = relu(z@Wu + bu) @ Wf + bf =================
__global__ void gemm_up_fused(const float* __restrict__ z,
                              const float* __restrict__ Wu,
                              const float* __restrict__ bu,
                              const float* __restrict__ Wf,
                              const float* __restrict__ bf,
                              float* __restrict__ gf) {
    __shared__ float As[BK][32 + 1];
    __shared__ float Bs[BK][HH];
    __shared__ float Hu[32][HH + 1];
    int tid = threadIdx.x;
    int m0 = blockIdx.x * 32;
    int tx = tid & 31, ty = tid >> 5;
    float acc[4][4] = {};
    for (int k0 = 0; k0 < HH; k0 += BK) {
        #pragma unroll
        for (int t = 0; t < 4; t++) {
            int li = tid + t * 256;
            int m = li >> 5, kk = li & 31;
            As[kk][m] = z[(size_t)(m0 + m) * HH + (k0 + kk)];
        }
        #pragma unroll
        for (int t = 0; t < 16; t++) {
            int li = tid + t * 256;
            int kk = li >> 7, n = li & 127;
            Bs[kk][n] = Wu[(size_t)(k0 + kk) * HH + n];
        }
        __syncthreads();
        #pragma unroll
        for (int kk = 0; kk < BK; kk++) {
            float a[4];
            #pragma unroll
            for (int i = 0; i < 4; i++) a[i] = As[kk][ty * 4 + i];
            float4 b4 = *(const float4*)&Bs[kk][tx * 4];
            #pragma unroll
            for (int i = 0; i < 4; i++) {
                acc[i][0] += a[i] * b4.x;
                acc[i][1] += a[i] * b4.y;
                acc[i][2] += a[i] * b4.z;
                acc[i][3] += a[i] * b4.w;
            }
        }
        __syncthreads();
    }
    {
        float4 bv = *(const float4*)&bu[tx * 4];
        #pragma unroll
        for (int i = 0; i < 4; i++) {
            Hu[ty * 4 + i][tx * 4 + 0] = fmaxf(acc[i][0] + bv.x, 0.0f);
            Hu[ty * 4 + i][tx * 4 + 1] = fmaxf(acc[i][1] + bv.y, 0.0f);
            Hu[ty * 4 + i][tx * 4 + 2] = fmaxf(acc[i][2] + bv.z, 0.0f);
            Hu[ty * 4 + i][tx * 4 + 3] = fmaxf(acc[i][3] + bv.w, 0.0f);
        }
    }
    __syncthreads();
    {
        int m = tid >> 3;
        int n2 = (tid & 7) * 2;
        float a0 = 0.f, a1 = 0.f;
        #pragma unroll 4
        for (int k = 0; k < HH; k++) {
            float h = Hu[m][k];
            float2 w = *(const float2*)&Wf[(size_t)k * FOUT + n2];
            a0 += h * w.x;
            a1 += h * w.y;
        }
        gf[(size_t)(m0 + m) * FOUT + n2]     = a0 + bf[n2];
        gf[(size_t)(m0 + m) * FOUT + n2 + 1] = a1 + bf[n2 + 1];
    }
}

// ---------------- final SpMM (F_OUT=16) + log_softmax, 2 rows/warp -----------
__global__ void spmm_out_kernel(const float* __restrict__ gf,
                                const int* __restrict__ deg,
                                float* __restrict__ out) {
    int r = blockIdx.x * (blockDim.x >> 4) + (threadIdx.x >> 4);
    int lane = threadIdx.x & 15;
    if (r >= NN) return;
    float acc0 = gf[(size_t)r * FOUT + lane];
    float acc1 = 0.0f;
    int dg = deg[r];
    dg = (dg < MAXDEG) ? dg : MAXDEG;
    const int* lst = d_ell + (size_t)r * MAXDEG;
    int t = 0;
    for (; t + 8 <= dg; t += 8) {
        int4 ia = *(const int4*)(lst + t);
        int4 ib = *(const int4*)(lst + t + 4);
        float v0 = gf[(size_t)ia.x * FOUT + lane];
        float v1 = gf[(size_t)ia.y * FOUT + lane];
        float v2 = gf[(size_t)ia.z * FOUT + lane];
        float v3 = gf[(size_t)ia.w * FOUT + lane];
        float v4 = gf[(size_t)ib.x * FOUT + lane];
        float v5 = gf[(size_t)ib.y * FOUT + lane];
        float v6 = gf[(size_t)ib.z * FOUT + lane];
        float v7 = gf[(size_t)ib.w * FOUT + lane];
        acc0 += v0 + v2 + v4 + v6;
        acc1 += v1 + v3 + v5 + v7;
    }
    for (; t < dg; t++) acc0 += gf[(size_t)lst[t] * FOUT + lane];
    float f = (acc0 + acc1) / (float)(1 + dg);
    float m = f;
    #pragma unroll
    for (int off = 8; off; off >>= 1) m = fmaxf(m, __shfl_xor_sync(0xffffffffu, m, off));
    float e = expf(f - m);
    float s = e;
    #pragma unroll
    for (int off = 8; off; off >>= 1) s += __shfl_xor_sync(0xffffffffu, s, off);
    out[(size_t)r * FOUT + lane] = f - m - logf(s);
}

// ---------------- host launcher ----------------------------------------------
extern "C" void kernel_launch(void* const* d_in, const int* in_sizes, int n_in,
                              void* d_out, int out_size) {
    const float* x  = (const float*)d_in[0];
    const float* A  = (const float*)d_in[1];
    const float* W0 = (const float*)d_in[2];
    const float* b0 = (const float*)d_in[3];
    const float* W1 = (const float*)d_in[4];
    const float* b1 = (const float*)d_in[5];
    const float* pw = (const float*)d_in[6];
    const float* pb = (const float*)d_in[7];
    const float* Wu = (const float*)d_in[8];
    const float* bu = (const float*)d_in[9];
    const float* Wf = (const float*)d_in[10];
    const float* bf = (const float*)d_in[11];
    float* out = (float*)d_out;

    void *p_ell, *p_deg, *p_g0, *p_h0, *p_s, *p_gate, *p_mask,
         *p_qh, *p_xuh, *p_z, *p_gf, *p_ctr;
    cudaGetSymbolAddress(&p_ell, d_ell);
    cudaGetSymbolAddress(&p_deg, d_deg);
    cudaGetSymbolAddress(&p_g0, d_g0);
    cudaGetSymbolAddress(&p_h0, d_h0);
    cudaGetSymbolAddress(&p_s, d_s);
    cudaGetSymbolAddress(&p_gate, d_gate);
    cudaGetSymbolAddress(&p_mask, d_mask);
    cudaGetSymbolAddress(&p_qh, d_qh);
    cudaGetSymbolAddress(&p_xuh, d_xuh);
    cudaGetSymbolAddress(&p_z, d_z);
    cudaGetSymbolAddress(&p_gf, d_gf);
    cudaGetSymbolAddress(&p_ctr, d_g0ctr);

    int* ell = (int*)p_ell;      int* deg = (int*)p_deg;
    float* g0 = (float*)p_g0;    float* h0 = (float*)p_h0;
    float* sarr = (float*)p_s;   float* gatev = (float*)p_gate;
    int* maskv = (int*)p_mask;
    __half* Qh = (__half*)p_qh;  __half* xuh = (__half*)p_xuh;
    float* zz = (float*)p_z;     float* gf = (float*)p_gf;

    // 0. reset barrier + degree counters (graph memset nodes; no allocation)
    cudaMemsetAsync(p_ctr, 0, sizeof(unsigned));
    cudaMemsetAsync(p_deg, 0, NN * sizeof(int));
    // 1. persistent K1: GEMM0 + symmetric scan -> barrier -> h0-agg + score
    k1_persistent<<<PGRID, 256>>>(A, x, W0, b0, pw, pb,
                                  ell, deg, g0, h0, sarr);
    // 2. selection overlapped with Q = h0@W1 (fp16 out; b0 is the zero bias)
    fused_select_gemmq<<<257, 256>>>(sarr, gatev, maskv, h0, W1, b0, Qh);
    // 3. pooled aggregation: fp16 gather (gate-predicated), fp16 xu out
    spmm_pool4h_kernel<<<NN / 2, 256>>>(Qh, deg, maskv, gatev, b1, xuh);
    // 4. z = norm_agg(xu): unconditional fp16 gather
    spmm4h_kernel<<<NN / 2, 256>>>(xuh, deg, zz);
    // 5. gf = relu(z@Wu + bu) @ Wf + bf
    gemm_up_fused<<<NN / 32, 256>>>(zz, Wu, bu, Wf, bf, gf);
    // 6. out = log_softmax(norm_agg(gf))
    spmm_out_kernel<<<NN / 16, 256>>>(gf, deg, out);

    (void)in_sizes; (void)n_in; (void)out_size;
}

// round 17
// speedup vs baseline: 1.3305x; 1.3305x over previous
#include <cuda_runtime.h>
#include <cuda_fp16.h>
#include <math.h>

#define NN 8192
#define HH 128
#define FOUT 16
#define MAXDEG 256
#define KSEL 4096
#define BM 64
#define BN 64
#define BK 32

// ---------------- scratch (device globals; no allocation) ----------------
__device__ int      d_ell[(size_t)NN * MAXDEG];
__device__ int      d_deg[NN];
__device__ float    d_g0[(size_t)NN * HH];
__device__ float    d_h0[(size_t)NN * HH];
__device__ float    d_s[NN];
__device__ float    d_gate[NN];
__device__ int      d_mask[NN];
__device__ __half   d_qh[(size_t)NN * HH];
__device__ __half   d_xuh[(size_t)NN * HH];
__device__ float    d_z[(size_t)NN * HH];
__device__ float    d_gf[(size_t)NN * FOUT];
__device__ unsigned d_g0ctr;

// ---------------- shared layouts ----------------
struct GemmSh {
    float As[BK][BM + 1];
    float Bs[BK][BN];
};
struct SelSh {
    unsigned keys[NN];
    unsigned whist[8][256];
    unsigned suf[256];
    unsigned cnts[8];
    unsigned prefix, kk;
    float    inv_norm;
    float    red[8];
};
union SharedU {
    GemmSh g;
    SelSh  s;
};

#define ACC4(a, v) { (a).x += (v).x; (a).y += (v).y; (a).z += (v).z; (a).w += (v).w; }
#define FMA4(a, g, v) { (a).x += (g)*(v).x; (a).y += (g)*(v).y; (a).z += (g)*(v).z; (a).w += (g)*(v).w; }

// ---------------- half-row gather helper ----------------
__device__ __forceinline__ float4 ldh4(const uint2* __restrict__ base, size_t row, int lane) {
    uint2 u = base[row * 32 + lane];
    __half2 h0 = *reinterpret_cast<__half2*>(&u.x);
    __half2 h1 = *reinterpret_cast<__half2*>(&u.y);
    float2 f0 = __half22float2(h0);
    float2 f1 = __half22float2(h1);
    return make_float4(f0.x, f0.y, f1.x, f1.y);
}

// ---------------- GEMM body (templated fp32/fp16 output) ----------------
template <bool HALFOUT>
__device__ __forceinline__ void gemm_body(GemmSh& sh,
                                          const float* __restrict__ Ain,
                                          const float* __restrict__ B,
                                          const float* __restrict__ bias,
                                          void* __restrict__ C,
                                          int K, int Nc, int m0, int n0) {
    int tid = threadIdx.x;
    int tx = tid & 15, ty = tid >> 4;
    float acc[4][4] = {};
    for (int k0 = 0; k0 < K; k0 += BK) {
        #pragma unroll
        for (int t = 0; t < 8; t++) {
            int li = tid + t * 256;
            int m = li >> 5, kk = li & 31;
            sh.As[kk][m] = Ain[(size_t)(m0 + m) * K + (k0 + kk)];
        }
        #pragma unroll
        for (int t = 0; t < 8; t++) {
            int li = tid + t * 256;
            int kk = li >> 6, n = li & 63;
            sh.Bs[kk][n] = (n0 + n < Nc) ? B[(size_t)(k0 + kk) * Nc + (n0 + n)] : 0.0f;
        }
        __syncthreads();
        #pragma unroll
        for (int kk = 0; kk < BK; kk++) {
            float a[4], b[4];
            #pragma unroll
            for (int i = 0; i < 4; i++) a[i] = sh.As[kk][ty * 4 + i];
            #pragma unroll
            for (int j = 0; j < 4; j++) b[j] = sh.Bs[kk][tx * 4 + j];
            #pragma unroll
            for (int i = 0; i < 4; i++)
                #pragma unroll
                for (int j = 0; j < 4; j++)
                    acc[i][j] += a[i] * b[j];
        }
        __syncthreads();
    }
    #pragma unroll
    for (int i = 0; i < 4; i++) {
        int m = m0 + ty * 4 + i;
        #pragma unroll
        for (int j = 0; j < 4; j++) {
            int n = n0 + tx * 4 + j;
            if (n < Nc) {
                float v = acc[i][j] + bias[n];
                if (HALFOUT) ((__half*)C)[(size_t)m * Nc + n] = __float2half(v);
                else         ((float*)C)[(size_t)m * Nc + n] = v;
            }
        }
    }
}

// ======== kernel 1: GEMM0 (blocks 0..255) || ELL build + h0-agg + score ======
__global__ void fused_ell_gemm0_spmm(const float* __restrict__ A,
                                     const float* __restrict__ x,
                                     const float* __restrict__ W0,
                                     const float* __restrict__ b0,
                                     const float* __restrict__ pw,
                                     const float* __restrict__ pbp,
                                     int* __restrict__ ell, int* __restrict__ deg,
                                     float* __restrict__ g0,
                                     float* __restrict__ h0,
                                     float* __restrict__ score) {
    __shared__ GemmSh sh;
    int b = blockIdx.x;
    if (b < 256) {
        gemm_body<false>(sh, x, W0, b0, g0, 256, HH, (b >> 1) * BM, (b & 1) * BN);
        __threadfence();
        __syncthreads();
        if (threadIdx.x == 0) atomicAdd(&d_g0ctr, 1u);
        return;
    }
    // ---- ELL build: one warp per row ----
    int rg = b - 256;
    int wid = threadIdx.x >> 5;
    int lane = threadIdx.x & 31;
    int r = rg * 8 + wid;
    const float* row = A + (size_t)r * NN;
    int* lst = ell + (size_t)r * MAXDEG;
    int cnt = 0;
    for (int c0 = 0; c0 < NN; c0 += 128) {
        float4 v = *(const float4*)(row + c0 + lane * 4);
        #pragma unroll
        for (int u = 0; u < 4; u++) {
            float xv = (&v.x)[u];
            unsigned bl = __ballot_sync(0xffffffffu, xv != 0.0f);
            if (xv != 0.0f) {
                int pos = cnt + __popc(bl & ((1u << lane) - 1u));
                if (pos < MAXDEG) lst[pos] = c0 + lane * 4 + u;
            }
            cnt += __popc(bl);
        }
    }
    int dg = (cnt < MAXDEG) ? cnt : MAXDEG;
    if (lane == 0) deg[r] = dg;

    // ---- wait for g0 (GEMM blocks are ids 0..255 -> dispatched first; safe) ----
    if (threadIdx.x == 0) {
        while (atomicAdd(&d_g0ctr, 0u) < 256u) __nanosleep(64);
    }
    __syncthreads();
    __threadfence();

    // ---- h0[r] = relu((g0[r] + sum_nbr g0[j]) / (1+deg)); score ----
    const float4* g4 = (const float4*)g0;
    float4 acc0 = g4[(size_t)r * 32 + lane];
    float4 acc1 = {0.f, 0.f, 0.f, 0.f};
    int t = 0;
    for (; t + 8 <= dg; t += 8) {
        int4 ia = *(const int4*)(lst + t);
        int4 ib = *(const int4*)(lst + t + 4);
        float4 v0 = g4[(size_t)ia.x * 32 + lane];
        float4 v1 = g4[(size_t)ia.y * 32 + lane];
        float4 v2 = g4[(size_t)ia.z * 32 + lane];
        float4 v3 = g4[(size_t)ia.w * 32 + lane];
        float4 v4 = g4[(size_t)ib.x * 32 + lane];
        float4 v5 = g4[(size_t)ib.y * 32 + lane];
        float4 v6 = g4[(size_t)ib.z * 32 + lane];
        float4 v7 = g4[(size_t)ib.w * 32 + lane];
        ACC4(acc0, v0); ACC4(acc1, v1); ACC4(acc0, v2); ACC4(acc1, v3);
        ACC4(acc0, v4); ACC4(acc1, v5); ACC4(acc0, v6); ACC4(acc1, v7);
    }
    for (; t < dg; t++) {
        float4 v = g4[(size_t)lst[t] * 32 + lane];
        ACC4(acc0, v);
    }
    ACC4(acc0, acc1);
    float sc = 1.0f / (float)(1 + dg);
    acc0.x = fmaxf(acc0.x * sc, 0.0f);
    acc0.y = fmaxf(acc0.y * sc, 0.0f);
    acc0.z = fmaxf(acc0.z * sc, 0.0f);
    acc0.w = fmaxf(acc0.w * sc, 0.0f);
    ((float4*)h0)[(size_t)r * 32 + lane] = acc0;
    float4 w = ((const float4*)pw)[lane];
    float dd = acc0.x * w.x + acc0.y * w.y + acc0.z * w.z + acc0.w * w.w;
    #pragma unroll
    for (int off = 16; off; off >>= 1) dd += __shfl_xor_sync(0xffffffffu, dd, off);
    if (lane == 0) score[r] = dd + pbp[0];
}

// ---------------- selection body ----------------
__device__ __forceinline__ void select_body(SelSh& sh,
                                            const float* __restrict__ s,
                                            float* __restrict__ gate,
                                            int* __restrict__ mask) {
    int t = threadIdx.x;
    int warp = t >> 5, lane = t & 31;

    float ss = 0.0f;
    for (int i = t; i < NN; i += 256) {
        float v = s[i];
        unsigned u = __float_as_uint(v);
        u = (u & 0x80000000u) ? ~u : (u | 0x80000000u);
        sh.keys[i] = u;
        ss += v * v;
    }
    #pragma unroll
    for (int off = 16; off; off >>= 1) ss += __shfl_xor_sync(0xffffffffu, ss, off);
    if (lane == 0) sh.red[warp] = ss;
    __syncthreads();
    if (t == 0) {
        float tot = 0.0f;
        #pragma unroll
        for (int w = 0; w < 8; w++) tot += sh.red[w];
        sh.inv_norm = rsqrtf(tot);
        sh.prefix = 0;
        sh.kk = KSEL;
    }
    __syncthreads();

    unsigned maskbits = 0;
    for (int shift = 24; shift >= 0; shift -= 8) {
        for (int i = t; i < 8 * 256; i += 256) ((unsigned*)sh.whist)[i] = 0;
        __syncthreads();
        unsigned pref = sh.prefix;
        for (int i = t; i < NN; i += 256) {
            unsigned ky = sh.keys[i];
            if ((ky & maskbits) == pref)
                atomicAdd(&sh.whist[warp][(ky >> shift) & 255u], 1u);
        }
        __syncthreads();
        {
            unsigned h = 0;
            #pragma unroll
            for (int w = 0; w < 8; w++) h += sh.whist[w][t];
            sh.suf[t] = h;
        }
        __syncthreads();
        for (int off = 1; off < 256; off <<= 1) {
            unsigned v = sh.suf[t] + ((t + off < 256) ? sh.suf[t + off] : 0u);
            __syncthreads();
            sh.suf[t] = v;
            __syncthreads();
        }
        unsigned Sb  = sh.suf[t];
        unsigned Sb1 = (t < 255) ? sh.suf[t + 1] : 0u;
        unsigned kkv = sh.kk;
        __syncthreads();
        if (Sb >= kkv && Sb1 < kkv) {
            sh.prefix = pref | ((unsigned)t << shift);
            sh.kk = kkv - Sb1;
        }
        maskbits |= (0xFFu << shift);
        __syncthreads();
    }
    unsigned T = sh.prefix;
    unsigned need_eq = sh.kk;
    float inv_norm = sh.inv_norm;

    int base = t * 32;
    unsigned loc = 0;
    #pragma unroll
    for (int u = 0; u < 32; u++) loc += (sh.keys[base + u] == T) ? 1u : 0u;
    unsigned inc = loc;
    #pragma unroll
    for (int off = 1; off < 32; off <<= 1) {
        unsigned v = __shfl_up_sync(0xffffffffu, inc, off);
        if (lane >= off) inc += v;
    }
    if (lane == 31) sh.cnts[warp] = inc;
    __syncthreads();
    unsigned woff = 0;
    for (int w = 0; w < warp; w++) woff += sh.cnts[w];
    unsigned run = woff + inc - loc;

    #pragma unroll
    for (int u = 0; u < 32; u++) {
        int i = base + u;
        unsigned ky = sh.keys[i];
        int sel;
        if (ky > T) sel = 1;
        else if (ky == T) { sel = (run < need_eq) ? 1 : 0; run++; }
        else sel = 0;
        mask[i] = sel;
        float v = s[i] * inv_norm;
        gate[i] = sel ? (1.0f / (1.0f + expf(-v))) : 0.0f;
    }
}

// ---------------- fused kernel 2: select || Q = h0@W1 (fp16 out) -------------
__global__ void fused_select_gemmq(const float* __restrict__ s,
                                   float* __restrict__ gate, int* __restrict__ mask,
                                   const float* __restrict__ h0,
                                   const float* __restrict__ W1,
                                   const float* __restrict__ zero_bias,
                                   __half* __restrict__ Qh) {
    __shared__ SharedU sh;
    int b = blockIdx.x;
    if (b == 0) {
        select_body(sh.s, s, gate, mask);
    } else {
        int bb = b - 1;
        gemm_body<true>(sh.g, h0, W1, zero_bias, Qh, HH, HH, (bb >> 1) * BM, (bb & 1) * BN);
    }
}

// ======== pooled SpMM: UNCONDITIONAL fp16 gathers, gate as weight+mask =======
// Qh holds Q = h0@W1 for ALL rows; gate[j]==0 exactly iff j unselected, so
// gathering every neighbor and weighting by gate[j] is bit-identical to the
// predicated version while keeping the spmm4h instruction profile.
__global__ void __launch_bounds__(256)
spmm_pool4h_kernel(const __half* __restrict__ Q,
                   const int* __restrict__ deg,
                   const int* __restrict__ mask,
                   const float* __restrict__ gate,
                   const float* __restrict__ b1,
                   __half* __restrict__ xu) {
    __shared__ float4 part[8][32];
    __shared__ int    pcnt[8];
    int wid = threadIdx.x >> 5;
    int lane = threadIdx.x & 31;
    int rw = wid >> 2;
    int wq = wid & 3;
    int r = blockIdx.x * 2 + rw;
    int active = mask[r];
    const uint2* q2 = (const uint2*)Q;
    int dg = deg[r];
    const int* lst = d_ell + (size_t)r * MAXDEG;

    float4 acc0 = {0.f, 0.f, 0.f, 0.f};
    float4 acc1 = {0.f, 0.f, 0.f, 0.f};
    int cnt = 0;
    if (active) {
        if (wq == 0) {
            float gr = gate[r];
            float4 v = ldh4(q2, (size_t)r, lane);
            FMA4(acc0, gr, v);
            cnt = 1;
        }
        int beg = (dg * wq) >> 2;
        int end = (dg * (wq + 1)) >> 2;
        int t = beg;
        for (; t + 8 <= end; t += 8) {
            int j0 = lst[t], j1 = lst[t+1], j2 = lst[t+2], j3 = lst[t+3];
            int j4 = lst[t+4], j5 = lst[t+5], j6 = lst[t+6], j7 = lst[t+7];
            float g0v = gate[j0], g1v = gate[j1], g2v = gate[j2], g3v = gate[j3];
            float g4v = gate[j4], g5v = gate[j5], g6v = gate[j6], g7v = gate[j7];
            float4 v0 = ldh4(q2, (size_t)j0, lane);
            float4 v1 = ldh4(q2, (size_t)j1, lane);
            float4 v2 = ldh4(q2, (size_t)j2, lane);
            float4 v3 = ldh4(q2, (size_t)j3, lane);
            float4 v4 = ldh4(q2, (size_t)j4, lane);
            float4 v5 = ldh4(q2, (size_t)j5, lane);
            float4 v6 = ldh4(q2, (size_t)j6, lane);
            float4 v7 = ldh4(q2, (size_t)j7, lane);
            FMA4(acc0, g0v, v0); FMA4(acc1, g1v, v1);
            FMA4(acc0, g2v, v2); FMA4(acc1, g3v, v3);
            FMA4(acc0, g4v, v4); FMA4(acc1, g5v, v5);
            FMA4(acc0, g6v, v6); FMA4(acc1, g7v, v7);
            cnt += (g0v != 0.0f) + (g1v != 0.0f) + (g2v != 0.0f) + (g3v != 0.0f)
                 + (g4v != 0.0f) + (g5v != 0.0f) + (g6v != 0.0f) + (g7v != 0.0f);
        }
        for (; t < end; t++) {
            int j = lst[t];
            float gj = gate[j];
            float4 v = ldh4(q2, (size_t)j, lane);
            FMA4(acc0, gj, v);
            cnt += (gj != 0.0f);
        }
        ACC4(acc0, acc1);
    }
    part[wid][lane] = acc0;
    if (lane == 0) pcnt[wid] = cnt;
    __syncthreads();
    if (wq == 0) {
        uint2* o2 = (uint2*)xu;
        if (!active) {
            uint2 z = {0u, 0u};
            o2[(size_t)r * 32 + lane] = z;
        } else {
            float4 a = part[rw * 4 + 0][lane];
            float4 b = part[rw * 4 + 1][lane];
            float4 c = part[rw * 4 + 2][lane];
            float4 d = part[rw * 4 + 3][lane];
            float4 s;
            s.x = a.x + b.x + c.x + d.x;
            s.y = a.y + b.y + c.y + d.y;
            s.z = a.z + b.z + c.z + d.z;
            s.w = a.w + b.w + c.w + d.w;
            int ctot = pcnt[rw*4+0] + pcnt[rw*4+1] + pcnt[rw*4+2] + pcnt[rw*4+3];
            float sc = 1.0f / (float)ctot;
            float4 bv = ((const float4*)b1)[lane];
            s.x = fmaxf(s.x * sc + bv.x, 0.0f);
            s.y = fmaxf(s.y * sc + bv.y, 0.0f);
            s.z = fmaxf(s.z * sc + bv.z, 0.0f);
            s.w = fmaxf(s.w * sc + bv.w, 0.0f);
            __half2 h0 = __floats2half2_rn(s.x, s.y);
            __half2 h1 = __floats2half2_rn(s.z, s.w);
            uint2 o;
            o.x = *reinterpret_cast<unsigned*>(&h0);
            o.y = *reinterpret_cast<unsigned*>(&h1);
            o2[(size_t)r * 32 + lane] = o;
        }
    }
}

// ======== z = norm_agg(xu): fully unconditional fp16 gather ==================
__global__ void __launch_bounds__(256)
spmm4h_kernel(const __half* __restrict__ xu,
              const int* __restrict__ deg,
              float* __restrict__ z) {
    __shared__ float4 part[8][32];
    int wid = threadIdx.x >> 5;
    int lane = threadIdx.x & 31;
    int rw = wid >> 2;
    int wq = wid & 3;
    int r = blockIdx.x * 2 + rw;
    const uint2* x2 = (const uint2*)xu;
    int dg = deg[r];
    const int* lst = d_ell + (size_t)r * MAXDEG;
    int beg = (dg * wq) >> 2;
    int end = (dg * (wq + 1)) >> 2;

    float4 acc0 = {0.f, 0.f, 0.f, 0.f};
    float4 acc1 = {0.f, 0.f, 0.f, 0.f};
    if (wq == 0) acc0 = ldh4(x2, (size_t)r, lane);
    int t = beg;
    for (; t + 8 <= end; t += 8) {
        int j0 = lst[t], j1 = lst[t+1], j2 = lst[t+2], j3 = lst[t+3];
        int j4 = lst[t+4], j5 = lst[t+5], j6 = lst[t+6], j7 = lst[t+7];
        float4 v0 = ldh4(x2, (size_t)j0, lane);
        float4 v1 = ldh4(x2, (size_t)j1, lane);
        float4 v2 = ldh4(x2, (size_t)j2, lane);
        float4 v3 = ldh4(x2, (size_t)j3, lane);
        float4 v4 = ldh4(x2, (size_t)j4, lane);
        float4 v5 = ldh4(x2, (size_t)j5, lane);
        float4 v6 = ldh4(x2, (size_t)j6, lane);
        float4 v7 = ldh4(x2, (size_t)j7, lane);
        ACC4(acc0, v0); ACC4(acc1, v1); ACC4(acc0, v2); ACC4(acc1, v3);
        ACC4(acc0, v4); ACC4(acc1, v5); ACC4(acc0, v6); ACC4(acc1, v7);
    }
    for (; t < end; t++) {
        float4 v = ldh4(x2, (size_t)lst[t], lane);
        ACC4(acc0, v);
    }
    ACC4(acc0, acc1);
    part[wid][lane] = acc0;
    __syncthreads();
    if (wq == 0) {
        float4 a = part[rw * 4 + 0][lane];
        float4 b = part[rw * 4 + 1][lane];
        float4 c = part[rw * 4 + 2][lane];
        float4 d = part[rw * 4 + 3][lane];
        float4 s;
        s.x = a.x + b.x + c.x + d.x;
        s.y = a.y + b.y + c.y + d.y;
        s.z = a.z + b.z + c.z + d.z;
        s.w = a.w + b.w + c.w + d.w;
        float sc = 1.0f / (float)(1 + dg);
        s.x *= sc; s.y *= sc; s.z *= sc; s.w *= sc;
        ((float4*)z)[(size_t)r * 32 + lane] = s;
    }
}

// ======== fused up-path GEMM: gf = relu(z@Wu + bu) @ Wf + bf =================
__global__ void gemm_up_fused(const float* __restrict__ z,
                              const float* __restrict__ Wu,
                              const float* __restrict__ bu,
                              const float* __restrict__ Wf,
                              const float* __restrict__ bf,
                              float* __restrict__ gf) {
    __shared__ float As[BK][32 + 1];
    __shared__ float Bs[BK][HH];
    __shared__ float Hu[32][HH + 1];
    int tid = threadIdx.x;
    int m0 = blockIdx.x * 32;
    int tx = tid & 31, ty = tid >> 5;
    float acc[4][4] = {};
    for (int k0 = 0; k0 < HH; k0 += BK) {
        #pragma unroll
        for (int t = 0; t < 4; t++) {
            int li = tid + t * 256;
            int m = li >> 5, kk = li & 31;
            As[kk][m] = z[(size_t)(m0 + m) * HH + (k0 + kk)];
        }
        #pragma unroll
        for (int t = 0; t < 16; t++) {
            int li = tid + t * 256;
            int kk = li >> 7, n = li & 127;
            Bs[kk][n] = Wu[(size_t)(k0 + kk) * HH + n];
        }
        __syncthreads();
        #pragma unroll
        for (int kk = 0; kk < BK; kk++) {
            float a[4];
            #pragma unroll
            for (int i = 0; i < 4; i++) a[i] = As[kk][ty * 4 + i];
            float4 b4 = *(const float4*)&Bs[kk][tx * 4];
            #pragma unroll
            for (int i = 0; i < 4; i++) {
                acc[i][0] += a[i] * b4.x;
                acc[i][1] += a[i] * b4.y;
                acc[i][2] += a[i] * b4.z;
                acc[i][3] += a[i] * b4.w;
            }
        }
        __syncthreads();
    }
    {
        float4 bv = *(const float4*)&bu[tx * 4];
        #pragma unroll
        for (int i = 0; i < 4; i++) {
            Hu[ty * 4 + i][tx * 4 + 0] = fmaxf(acc[i][0] + bv.x, 0.0f);
            Hu[ty * 4 + i][tx * 4 + 1] = fmaxf(acc[i][1] + bv.y, 0.0f);
            Hu[ty * 4 + i][tx * 4 + 2] = fmaxf(acc[i][2] + bv.z, 0.0f);
            Hu[ty * 4 + i][tx * 4 + 3] = fmaxf(acc[i][3] + bv.w, 0.0f);
        }
    }
    __syncthreads();
    {
        int m = tid >> 3;
        int n2 = (tid & 7) * 2;
        float a0 = 0.f, a1 = 0.f;
        #pragma unroll 4
        for (int k = 0; k < HH; k++) {
            float h = Hu[m][k];
            float2 w = *(const float2*)&Wf[(size_t)k * FOUT + n2];
            a0 += h * w.x;
            a1 += h * w.y;
        }
        gf[(size_t)(m0 + m) * FOUT + n2]     = a0 + bf[n2];
        gf[(size_t)(m0 + m) * FOUT + n2 + 1] = a1 + bf[n2 + 1];
    }
}

// ---------------- final SpMM (F_OUT=16) + log_softmax, 2 rows/warp -----------
__global__ void spmm_out_kernel(const float* __restrict__ gf,
                                const int* __restrict__ deg,
                                float* __restrict__ out) {
    int r = blockIdx.x * (blockDim.x >> 4) + (threadIdx.x >> 4);
    int lane = threadIdx.x & 15;
    if (r >= NN) return;
    float acc0 = gf[(size_t)r * FOUT + lane];
    float acc1 = 0.0f;
    int dg = deg[r];
    const int* lst = d_ell + (size_t)r * MAXDEG;
    int t = 0;
    for (; t + 8 <= dg; t += 8) {
        int4 ia = *(const int4*)(lst + t);
        int4 ib = *(const int4*)(lst + t + 4);
        float v0 = gf[(size_t)ia.x * FOUT + lane];
        float v1 = gf[(size_t)ia.y * FOUT + lane];
        float v2 = gf[(size_t)ia.z * FOUT + lane];
        float v3 = gf[(size_t)ia.w * FOUT + lane];
        float v4 = gf[(size_t)ib.x * FOUT + lane];
        float v5 = gf[(size_t)ib.y * FOUT + lane];
        float v6 = gf[(size_t)ib.z * FOUT + lane];
        float v7 = gf[(size_t)ib.w * FOUT + lane];
        acc0 += v0 + v2 + v4 + v6;
        acc1 += v1 + v3 + v5 + v7;
    }
    for (; t < dg; t++) acc0 += gf[(size_t)lst[t] * FOUT + lane];
    float f = (acc0 + acc1) / (float)(1 + dg);
    float m = f;
    #pragma unroll
    for (int off = 8; off; off >>= 1) m = fmaxf(m, __shfl_xor_sync(0xffffffffu, m, off));
    float e = expf(f - m);
    float s = e;
    #pragma unroll
    for (int off = 8; off; off >>= 1) s += __shfl_xor_sync(0xffffffffu, s, off);
    out[(size_t)r * FOUT + lane] = f - m - logf(s);
}

// ---------------- host launcher ----------------------------------------------
extern "C" void kernel_launch(void* const* d_in, const int* in_sizes, int n_in,
                              void* d_out, int out_size) {
    const float* x  = (const float*)d_in[0];
    const float* A  = (const float*)d_in[1];
    const float* W0 = (const float*)d_in[2];
    const float* b0 = (const float*)d_in[3];
    const float* W1 = (const float*)d_in[4];
    const float* b1 = (const float*)d_in[5];
    const float* pw = (const float*)d_in[6];
    const float* pb = (const float*)d_in[7];
    const float* Wu = (const float*)d_in[8];
    const float* bu = (const float*)d_in[9];
    const float* Wf = (const float*)d_in[10];
    const float* bf = (const float*)d_in[11];
    float* out = (float*)d_out;

    void *p_ell, *p_deg, *p_g0, *p_h0, *p_s, *p_gate, *p_mask,
         *p_qh, *p_xuh, *p_z, *p_gf, *p_ctr;
    cudaGetSymbolAddress(&p_ell, d_ell);
    cudaGetSymbolAddress(&p_deg, d_deg);
    cudaGetSymbolAddress(&p_g0, d_g0);
    cudaGetSymbolAddress(&p_h0, d_h0);
    cudaGetSymbolAddress(&p_s, d_s);
    cudaGetSymbolAddress(&p_gate, d_gate);
    cudaGetSymbolAddress(&p_mask, d_mask);
    cudaGetSymbolAddress(&p_qh, d_qh);
    cudaGetSymbolAddress(&p_xuh, d_xuh);
    cudaGetSymbolAddress(&p_z, d_z);
    cudaGetSymbolAddress(&p_gf, d_gf);
    cudaGetSymbolAddress(&p_ctr, d_g0ctr);

    int* ell = (int*)p_ell;      int* deg = (int*)p_deg;
    float* g0 = (float*)p_g0;    float* h0 = (float*)p_h0;
    float* sarr = (float*)p_s;   float* gatev = (float*)p_gate;
    int* maskv = (int*)p_mask;
    __half* Qh = (__half*)p_qh;  __half* xuh = (__half*)p_xuh;
    float* zz = (float*)p_z;     float* gf = (float*)p_gf;

    // 0. reset the g0-completion counter (graph memset node; no allocation)
    cudaMemsetAsync(p_ctr, 0, sizeof(unsigned));
    // 1. GEMM0 || ELL build, then fused h0-aggregation + score behind counter
    fused_ell_gemm0_spmm<<<1280, 256>>>(A, x, W0, b0, pw, pb,
                                        ell, deg, g0, h0, sarr);
    // 2. selection overlapped with Q = h0@W1 (fp16 out; b0 is the zero bias)
    fused_select_gemmq<<<257, 256>>>(sarr, gatev, maskv, h0, W1, b0, Qh);
    // 3. pooled aggregation: unconditional fp16 gathers, gate-weighted
    spmm_pool4h_kernel<<<NN / 2, 256>>>(Qh, deg, maskv, gatev, b1, xuh);
    // 4. z = norm_agg(xu): unconditional fp16 gather
    spmm4h_kernel<<<NN / 2, 256>>>(xuh, deg, zz);
    // 5. gf = relu(z@Wu + bu) @ Wf + bf
    gemm_up_fused<<<NN / 32, 256>>>(zz, Wu, bu, Wf, bf, gf);
    // 6. out = log_softmax(norm_agg(gf))
    spmm_out_kernel<<<NN / 16, 256>>>(gf, deg, out);

    (void)in_sizes; (void)n_in; (void)out_size;
}